// round 14
// baseline (speedup 1.0000x reference)
#include <cuda_runtime.h>
#include <math.h>

// Fixed problem shapes
#define BB 8
#define CC 3
#define HF 1024
#define WF 2048
#define MM 32
#define HH 128
#define WW 256
#define HW (HH*WW)

// padded pooled image (2-px zero border each side)
#define PW (WW+4)
#define PH (HH+4)

#define NCH 128
#define CHSZ (HW/NCH)              // 256 samples per chunk
#define WIN  (3*CHSZ)              // 768-wide contiguous j-window
#define HALO 257

#define BORDER_PER_B (4*PW + 4*HH)             // 1552
#define BORDER_ELEMS (BB*BORDER_PER_B)         // 12416

#define PLANE_BLKS (BB*NCH)                    // 1024
#define POOL_PB    (CC*HH*WW/32)               // 3072 pool blocks per batch
#define BCHUNK     2                           // batches per pipeline chunk
#define NCHUNK     (BB/BCHUNK)                 // 4 chunks
#define BLEND_PB   32                          // blend blocks per batch (4px/thread)

// ---------------- scratch ----------------------------------------------------
__device__ float4 g_imgp[BB*PH*PW];          // padded pooled image
__device__ float  g_Hm  [BB*MM*6];           // homography top-2 rows
__device__ float  g_part[BB*MM*5*NCH];       // partial sums [bm][5][NCH]

// ---------------- kernel 1: plane partials (1024 blocks) ---------------------
__global__ __launch_bounds__(256) void plane_kernel(const float* __restrict__ masks,
                                                    const float* __restrict__ disp,
                                                    const float* __restrict__ intrs,
                                                    const float* __restrict__ baseline) {
    __shared__ float  sdep[WIN + 2*HALO];    // 1282 floats
    __shared__ float4 sdn [CHSZ];
    int bid = blockIdx.x;
    int tid = threadIdx.x;

    int bb = bid / NCH, ch = bid % NCH;
    float f  = 0.5f*(intrs[bb*9 + 0] + intrs[bb*9 + 4]);
    float sc = baseline[bb] * f * (1.f/2048.f);
    const float* dsp = disp + (size_t)bb*HW;
    int S = ch*CHSZ;
    int jbase = 3*S;

    // phase 0: coalesced depth window
    for (int k = tid; k < WIN + 2*HALO; k += 256) {
        int jj = jbase + k - HALO;
        jj = min(max(jj, 0), 3*HW - 1);
        sdep[k] = __fdividef(sc, dsp[jj & (HW-1)]);
    }
    __syncthreads();

    // phase 1: normals from smem (faithful .view(B,h*w,3) reinterpret)
    for (int k = tid; k < CHSZ; k += 256) {
        int i = S + k;
        float4 v;
        v.x = __fdividef(sc, dsp[i]);
        int k3 = 3*k;
        float nv[3];
#pragma unroll
        for (int tc = 0; tc < 3; tc++) {
            int j  = jbase + k3 + tc;
            int c  = j >> 15;
            int p  = j & (HW-1);
            int px = p & (WW-1), py = p >> 8;
            int kk = HALO + k3 + tc;
            float dxp = (px < WW-1) ? sdep[kk+1]  : 0.f;
            float dxm = (px > 0)    ? sdep[kk-1]  : 0.f;
            float dyp = (py < HH-1) ? sdep[kk+WW] : 0.f;
            float dym = (py > 0)    ? sdep[kk-WW] : 0.f;
            float gx = 0.5f*(dxp - dxm);
            float gy = 0.5f*(dyp - dym);
            float inv = rsqrtf(gx*gx + gy*gy + 1.f);
            nv[tc] = (c == 0) ? -gx*inv : ((c == 1) ? -gy*inv : inv);
        }
        v.y = nv[0]; v.z = nv[1]; v.w = nv[2];
        sdn[k] = v;
    }
    __syncthreads();

    // phase 2: warp w handles planes w, w+8, w+16, w+24 over 256 samples
    int wrp = tid >> 5, lane = tid & 31;
    const float* mb = masks + (size_t)bb*MM*HW + (size_t)S;
#pragma unroll
    for (int mi = 0; mi < 4; mi++) {
        int m = wrp + mi*8;
        const float* mp = mb + (size_t)m*HW;
        float se=0.f, sd=0.f, s0=0.f, s1=0.f, s2=0.f;
#pragma unroll
        for (int jj = 0; jj < 8; jj++) {
            int k = lane + jj*32;
            float e = __expf(mp[k]);     // no max-sub: ratio-invariant, safe range
            float4 v = sdn[k];
            se += e;
            sd = fmaf(e, v.x, sd);
            s0 = fmaf(e, v.y, s0);
            s1 = fmaf(e, v.z, s1);
            s2 = fmaf(e, v.w, s2);
        }
#pragma unroll
        for (int off = 16; off; off >>= 1) {
            se += __shfl_down_sync(0xffffffffu, se, off);
            sd += __shfl_down_sync(0xffffffffu, sd, off);
            s0 += __shfl_down_sync(0xffffffffu, s0, off);
            s1 += __shfl_down_sync(0xffffffffu, s1, off);
            s2 += __shfl_down_sync(0xffffffffu, s2, off);
        }
        if (lane == 0) {
            float* pp = g_part + ((size_t)(bb*MM + m)*5)*NCH + ch;
            pp[0*NCH]=se; pp[1*NCH]=sd; pp[2*NCH]=s0; pp[3*NCH]=s1; pp[4*NCH]=s2;
        }
    }
}

// ---------------- kernel 2: pool for a 2-batch chunk -------------------------
__global__ __launch_bounds__(256) void pool_kernel(const float* __restrict__ img, int b0) {
    __shared__ float sm[256];
    int tid = threadIdx.x;
    int lane = tid & 31, r = tid >> 5;
    int b  = b0 + blockIdx.x / POOL_PB;
    int q  = blockIdx.x % POOL_PB;
    int l  = q * 32;
    int x0 = l & (WW-1);
    int t  = l >> 8;
    int y  = t & (HH-1);
    int c  = t >> 7;

    const float4* p = (const float4*)(img +
        (((size_t)(b*CC + c)*HF + (size_t)y*8 + r)*WF) + (size_t)(x0 + lane)*8);
    float4 a = __ldcs(p), q4 = __ldcs(p + 1);   // streaming: don't pollute L1
    sm[r*32 + lane] = a.x+a.y+a.z+a.w + q4.x+q4.y+q4.z+q4.w;
    __syncthreads();
    if (tid < 32) {
        float acc = 0.f;
#pragma unroll
        for (int rr = 0; rr < 8; rr++) acc += sm[rr*32 + tid];
        ((float*)&g_imgp[(size_t)b*PH*PW + (size_t)(y+2)*PW + (x0 + tid + 2)])[c]
            = acc * (1.f/64.f);
    }
}

// ---------------- kernel 3: finalize homographies + border zero --------------
__global__ void finalize_kernel(const float* __restrict__ intrs,
                                const float* __restrict__ baseline) {
    int bm = blockIdx.x;              // 256 blocks = (b,m)
    int c  = threadIdx.x;             // 64 threads
    int lane = c & 31, w = c >> 5;

    int gt = bm*64 + c;
    if (gt < BORDER_ELEMS) {
        int b = gt / BORDER_PER_B;
        int r = gt % BORDER_PER_B;
        int cell;
        if (r < 2*PW)       cell = r;
        else if (r < 4*PW)  cell = (PH-2)*PW + (r - 2*PW);
        else {
            int rr = r - 4*PW;
            int row = rr >> 2, col = rr & 3;
            int cc = (col < 2) ? col : (PW-4 + col);
            cell = (2+row)*PW + cc;
        }
        g_imgp[(size_t)b*PH*PW + cell] = make_float4(0.f,0.f,0.f,0.f);
    }

    const float* pp = g_part + (size_t)bm*5*NCH;
    float v[5];
#pragma unroll
    for (int s = 0; s < 5; s++) v[s] = pp[s*NCH + c] + pp[s*NCH + 64 + c];
#pragma unroll
    for (int off = 16; off; off >>= 1)
#pragma unroll
        for (int s = 0; s < 5; s++) v[s] += __shfl_down_sync(0xffffffffu, v[s], off);
    __shared__ float sw[2][5];
    if (lane == 0)
#pragma unroll
        for (int s = 0; s < 5; s++) sw[w][s] = v[s];
    __syncthreads();
    if (c == 0) {
        float se = sw[0][0]+sw[1][0];
        float sd = sw[0][1]+sw[1][1];
        float s0 = sw[0][2]+sw[1][2];
        float s1 = sw[0][3]+sw[1][3];
        float s2 = sw[0][4]+sw[1][4];
        int b = bm / MM;
        float inv = 1.f/se;
        float d  = sd*inv;
        float n0 = s0*inv, n1 = s1*inv, n2 = s2*inv;
        float f  = intrs[b*9+0], g = intrs[b*9+4];
        float cx = intrs[b*9+2], cy = intrs[b*9+5];
        float bl = baseline[b];
        float t0 = bl*n0/d, t1 = bl*n1/d, t2 = bl*n2/d;
        float* o = g_Hm + bm*6;
        o[0] = 1.f + cx*t0/f;
        o[1] = cx*t1/g;
        o[2] = cx*t2 - cx*cx*t0/f - cx*cy*t1/g;
        o[3] = cy*t0/f;
        o[4] = 1.f + cy*t1/g;
        o[5] = cy*t2 - cx*cy*t0/f - cy*cy*t1/g;
    }
}

// ---------------- kernel 4: blend, 4 px/thread --------------------------------
__global__ __launch_bounds__(256) void blend_kernel(const float* __restrict__ masks,
                                                    float* __restrict__ out, int b0) {
    __shared__ float4 sA4[MM][2];
    int bid = blockIdx.x;
    int b   = b0 + (bid >> 5);        // 32 blocks per batch
    int loc = bid & 31;               // 1024 px per block
    int tid = threadIdx.x;

    if (tid < MM) {
        const float* Hp = g_Hm + (b*MM + tid)*6;
        sA4[tid][0] = make_float4(127.5f*Hp[0], 127.5f*Hp[1], 127.5f*(Hp[2]+1.f), 0.f);
        sA4[tid][1] = make_float4(63.5f*Hp[3],  63.5f*Hp[4],  63.5f*(Hp[5]+1.f),  0.f);
    }
    __syncthreads();

    int y  = loc*4 + (tid >> 6);      // 4 rows per block
    int x0 = (tid & 63) * 4;          // 4 consecutive px per thread
    int pix0 = y*WW + x0;
    float gyy = fmaf((float)y, 2.f/(float)(HH-1), -1.f);
    float gx[4];
#pragma unroll
    for (int k = 0; k < 4; k++)
        gx[k] = fmaf((float)(x0+k), 2.f/(float)(WW-1), -1.f);

    const float* mbase = masks + (size_t)b*MM*HW + pix0;
    const float4* ip = g_imgp + (size_t)b*PH*PW;
    float se[4] = {0.f,0.f,0.f,0.f};
    float a0[4] = {0.f,0.f,0.f,0.f};
    float a1[4] = {0.f,0.f,0.f,0.f};
    float a2[4] = {0.f,0.f,0.f,0.f};

#pragma unroll 4
    for (int m = 0; m < MM; m++) {
        float4 mv = *(const float4*)(mbase + (size_t)m*HW);   // 4 masks, one LDG.128
        float4 cA = sA4[m][0];
        float4 cB = sA4[m][1];
        float u = fmaf(cA.y, gyy, cA.z);
        float v = fmaf(cB.y, gyy, cB.z);
        float ev[4] = { __expf(mv.x), __expf(mv.y), __expf(mv.z), __expf(mv.w) };
#pragma unroll
        for (int k = 0; k < 4; k++) {
            float e = ev[k];
            se[k] += e;
            float ix = fmaf(cA.x, gx[k], u);
            float iy = fmaf(cB.x, gx[k], v);
            float x0f = floorf(ix), y0f = floorf(iy);
            float wx = ix - x0f, wy = iy - y0f;
            int xc = (int)fminf(fmaxf(x0f, -2.f), (float)WW);
            int yc = (int)fminf(fmaxf(y0f, -2.f), (float)HH);
            const float4* p00 = ip + (size_t)(yc+2)*PW + (xc+2);
            float4 c00 = p00[0];
            float4 c10 = p00[1];
            float4 c01 = p00[PW];
            float4 c11 = p00[PW+1];
            float w11 = wx*wy;
            float w10 = wx - w11;
            float w01 = wy - w11;
            float w00 = 1.f - wx - w01;
            a0[k] = fmaf(e, c00.x*w00 + c10.x*w10 + c01.x*w01 + c11.x*w11, a0[k]);
            a1[k] = fmaf(e, c00.y*w00 + c10.y*w10 + c01.y*w01 + c11.y*w11, a1[k]);
            a2[k] = fmaf(e, c00.z*w00 + c10.z*w10 + c01.z*w01 + c11.z*w11, a2[k]);
        }
    }

    float4 o;
    float inv0 = 1.f/se[0], inv1 = 1.f/se[1], inv2 = 1.f/se[2], inv3 = 1.f/se[3];
    o = make_float4(a0[0]*inv0, a0[1]*inv1, a0[2]*inv2, a0[3]*inv3);
    *(float4*)(out + ((size_t)b*3 + 0)*HW + pix0) = o;
    o = make_float4(a1[0]*inv0, a1[1]*inv1, a1[2]*inv2, a1[3]*inv3);
    *(float4*)(out + ((size_t)b*3 + 1)*HW + pix0) = o;
    o = make_float4(a2[0]*inv0, a2[1]*inv1, a2[2]*inv2, a2[3]*inv3);
    *(float4*)(out + ((size_t)b*3 + 2)*HW + pix0) = o;
}

// ---------------- launch: chunked forked-stream pipeline (R12 structure) -----
extern "C" void kernel_launch(void* const* d_in, const int* in_sizes, int n_in,
                              void* d_out, int out_size) {
    const float* img      = (const float*)d_in[0];
    const float* masks    = (const float*)d_in[1];
    const float* disp     = (const float*)d_in[2];
    const float* intrs    = (const float*)d_in[3];
    const float* baseline = (const float*)d_in[4];
    float* out = (float*)d_out;

    // Fresh stream + events each call (capture-safe; intentionally not destroyed
    // so captured graph nodes stay valid; kernel_launch runs only a few times).
    cudaStream_t sB;
    cudaStreamCreateWithFlags(&sB, cudaStreamNonBlocking);
    cudaEvent_t eFork, ePool[NCHUNK];
    cudaEventCreateWithFlags(&eFork, cudaEventDisableTiming);
    for (int k = 0; k < NCHUNK; k++)
        cudaEventCreateWithFlags(&ePool[k], cudaEventDisableTiming);

    // fork: pool chunks on sB
    cudaEventRecord(eFork, 0);
    cudaStreamWaitEvent(sB, eFork, 0);
    for (int k = 0; k < NCHUNK; k++) {
        pool_kernel<<<BCHUNK*POOL_PB, 256, 0, sB>>>(img, k*BCHUNK);
        cudaEventRecord(ePool[k], sB);
    }

    // stream 0: plane partials -> homographies (+ border zero)
    plane_kernel<<<PLANE_BLKS, 256>>>(masks, disp, intrs, baseline);
    finalize_kernel<<<BB*MM, 64>>>(intrs, baseline);

    // join: blend chunk k after pool chunk k (finalize ordered by stream 0)
    for (int k = 0; k < NCHUNK; k++) {
        cudaStreamWaitEvent(0, ePool[k], 0);
        blend_kernel<<<BCHUNK*BLEND_PB, 256>>>(masks, out, k*BCHUNK);
    }
}

// round 15
// speedup vs baseline: 1.5312x; 1.5312x over previous
#include <cuda_runtime.h>
#include <math.h>

// Fixed problem shapes
#define BB 8
#define CC 3
#define HF 1024
#define WF 2048
#define MM 32
#define HH 128
#define WW 256
#define HW (HH*WW)

// padded pooled image (2-px zero border each side)
#define PW (WW+4)
#define PH (HH+4)

#define NCH 64
#define CHSZ (HW/NCH)              // 512 samples per chunk
#define WIN  (3*CHSZ)              // 1536-wide contiguous j-window
#define HALO 257

#define BORDER_PER_B (4*PW + 4*HH)             // 1552
#define BORDER_ELEMS (BB*BORDER_PER_B)         // 12416

#define PLANE_BLKS (BB*NCH)                    // 512
#define POOL_PB    (CC*HH*WW/32)               // 3072 32-px tiles per batch
#define BCHUNK     2                           // batches per pipeline chunk
#define NCHUNK     (BB/BCHUNK)                 // 4 chunks

// ---------------- scratch ----------------------------------------------------
__device__ float4 g_imgp[BB*PH*PW];          // padded pooled image
__device__ float  g_Hm  [BB*MM*6];           // homography top-2 rows
__device__ float  g_part[BB*MM*5*NCH];       // partial sums [bm][5][NCH]

// ---------------- kernel 1: plane partials -----------------------------------
__global__ __launch_bounds__(256) void plane_kernel(const float* __restrict__ masks,
                                                    const float* __restrict__ disp,
                                                    const float* __restrict__ intrs,
                                                    const float* __restrict__ baseline) {
    __shared__ float  sdep[WIN + 2*HALO];
    __shared__ float4 sdn [CHSZ];
    int bid = blockIdx.x;
    int tid = threadIdx.x;

    int bb = bid / NCH, ch = bid % NCH;
    float f  = 0.5f*(intrs[bb*9 + 0] + intrs[bb*9 + 4]);
    float sc = baseline[bb] * f * (1.f/2048.f);
    const float* dsp = disp + (size_t)bb*HW;
    int S = ch*CHSZ;
    int jbase = 3*S;

    // phase 0: coalesced depth window
    for (int k = tid; k < WIN + 2*HALO; k += 256) {
        int jj = jbase + k - HALO;
        jj = min(max(jj, 0), 3*HW - 1);
        sdep[k] = __fdividef(sc, dsp[jj & (HW-1)]);
    }
    __syncthreads();

    // phase 1: normals from smem (faithful .view(B,h*w,3) reinterpret)
    for (int k = tid; k < CHSZ; k += 256) {
        int i = S + k;
        float4 v;
        v.x = __fdividef(sc, dsp[i]);
        int k3 = 3*k;
        float nv[3];
#pragma unroll
        for (int tc = 0; tc < 3; tc++) {
            int j  = jbase + k3 + tc;
            int c  = j >> 15;
            int p  = j & (HW-1);
            int px = p & (WW-1), py = p >> 8;
            int kk = HALO + k3 + tc;
            float dxp = (px < WW-1) ? sdep[kk+1]  : 0.f;
            float dxm = (px > 0)    ? sdep[kk-1]  : 0.f;
            float dyp = (py < HH-1) ? sdep[kk+WW] : 0.f;
            float dym = (py > 0)    ? sdep[kk-WW] : 0.f;
            float gx = 0.5f*(dxp - dxm);
            float gy = 0.5f*(dyp - dym);
            float inv = rsqrtf(gx*gx + gy*gy + 1.f);
            nv[tc] = (c == 0) ? -gx*inv : ((c == 1) ? -gy*inv : inv);
        }
        v.y = nv[0]; v.z = nv[1]; v.w = nv[2];
        sdn[k] = v;
    }
    __syncthreads();

    // phase 2: warp w handles planes w, w+8, w+16, w+24
    int wrp = tid >> 5, lane = tid & 31;
    const float* mb = masks + (size_t)bb*MM*HW + (size_t)S;
#pragma unroll
    for (int mi = 0; mi < 4; mi++) {
        int m = wrp + mi*8;
        const float* mp = mb + (size_t)m*HW;
        float se=0.f, sd=0.f, s0=0.f, s1=0.f, s2=0.f;
#pragma unroll
        for (int jj = 0; jj < 16; jj++) {
            int k = lane + jj*32;
            float e = __expf(mp[k]);     // no max-sub: ratio-invariant, safe range
            float4 v = sdn[k];
            se += e;
            sd = fmaf(e, v.x, sd);
            s0 = fmaf(e, v.y, s0);
            s1 = fmaf(e, v.z, s1);
            s2 = fmaf(e, v.w, s2);
        }
#pragma unroll
        for (int off = 16; off; off >>= 1) {
            se += __shfl_down_sync(0xffffffffu, se, off);
            sd += __shfl_down_sync(0xffffffffu, sd, off);
            s0 += __shfl_down_sync(0xffffffffu, s0, off);
            s1 += __shfl_down_sync(0xffffffffu, s1, off);
            s2 += __shfl_down_sync(0xffffffffu, s2, off);
        }
        if (lane == 0) {
            float* pp = g_part + ((size_t)(bb*MM + m)*5)*NCH + ch;
            pp[0*NCH]=se; pp[1*NCH]=sd; pp[2*NCH]=s0; pp[3*NCH]=s1; pp[4*NCH]=s2;
        }
    }
}

// ---------------- kernel 2: pool, 512 thr / 2 blocks per SM ------------------
// Residency capped at 1024 threads/SM so concurrent plane/blend blocks can be
// placed in the remaining slots. Per-thread work identical to the proven pool
// (2 independent LDG.128); block covers two 32-px tiles.
__global__ __launch_bounds__(512, 2) void pool_kernel(const float* __restrict__ img, int b0) {
    __shared__ float sm[512];
    int tid  = threadIdx.x;
    int grp  = tid >> 8;              // 0/1: which 32-px tile
    int t    = tid & 255;
    int lane = t & 31, r = t >> 5;

    int q  = blockIdx.x*2 + grp;      // tile index within chunk
    int b  = b0 + q / POOL_PB;
    int qq = q % POOL_PB;
    int l  = qq * 32;
    int x0 = l & (WW-1);
    int tt = l >> 8;
    int y  = tt & (HH-1);
    int c  = tt >> 7;                 // 0..2

    const float4* p = (const float4*)(img +
        (((size_t)(b*CC + c)*HF + (size_t)y*8 + r)*WF) + (size_t)(x0 + lane)*8);
    float4 a = __ldcs(p), q4 = __ldcs(p + 1);   // streaming: don't pollute L1
    sm[grp*256 + r*32 + lane] = a.x+a.y+a.z+a.w + q4.x+q4.y+q4.z+q4.w;
    __syncthreads();
    if (t < 32) {
        float acc = 0.f;
#pragma unroll
        for (int rr = 0; rr < 8; rr++) acc += sm[grp*256 + rr*32 + t];
        ((float*)&g_imgp[(size_t)b*PH*PW + (size_t)(y+2)*PW + (x0 + t + 2)])[c]
            = acc * (1.f/64.f);
    }
}

// ---------------- kernel 3: finalize homographies + border zero --------------
__global__ void finalize_kernel(const float* __restrict__ intrs,
                                const float* __restrict__ baseline) {
    int bm = blockIdx.x;              // 256 blocks = (b,m)
    int c  = threadIdx.x;             // 64 threads
    int lane = c & 31, w = c >> 5;

    int gt = bm*64 + c;
    if (gt < BORDER_ELEMS) {
        int b = gt / BORDER_PER_B;
        int r = gt % BORDER_PER_B;
        int cell;
        if (r < 2*PW)       cell = r;
        else if (r < 4*PW)  cell = (PH-2)*PW + (r - 2*PW);
        else {
            int rr = r - 4*PW;
            int row = rr >> 2, col = rr & 3;
            int cc = (col < 2) ? col : (PW-4 + col);
            cell = (2+row)*PW + cc;
        }
        g_imgp[(size_t)b*PH*PW + cell] = make_float4(0.f,0.f,0.f,0.f);
    }

    const float* pp = g_part + (size_t)bm*5*NCH;
    float v[5];
#pragma unroll
    for (int s = 0; s < 5; s++) v[s] = pp[s*NCH + c];
#pragma unroll
    for (int off = 16; off; off >>= 1)
#pragma unroll
        for (int s = 0; s < 5; s++) v[s] += __shfl_down_sync(0xffffffffu, v[s], off);
    __shared__ float sw[2][5];
    if (lane == 0)
#pragma unroll
        for (int s = 0; s < 5; s++) sw[w][s] = v[s];
    __syncthreads();
    if (c == 0) {
        float se = sw[0][0]+sw[1][0];
        float sd = sw[0][1]+sw[1][1];
        float s0 = sw[0][2]+sw[1][2];
        float s1 = sw[0][3]+sw[1][3];
        float s2 = sw[0][4]+sw[1][4];
        int b = bm / MM;
        float inv = 1.f/se;
        float d  = sd*inv;
        float n0 = s0*inv, n1 = s1*inv, n2 = s2*inv;
        float f  = intrs[b*9+0], g = intrs[b*9+4];
        float cx = intrs[b*9+2], cy = intrs[b*9+5];
        float bl = baseline[b];
        float t0 = bl*n0/d, t1 = bl*n1/d, t2 = bl*n2/d;
        float* o = g_Hm + bm*6;
        o[0] = 1.f + cx*t0/f;
        o[1] = cx*t1/g;
        o[2] = cx*t2 - cx*cx*t0/f - cx*cy*t1/g;
        o[3] = cy*t0/f;
        o[4] = 1.f + cy*t1/g;
        o[5] = cy*t2 - cx*cy*t0/f - cy*cy*t1/g;
    }
}

// ---------------- kernel 4: blend for a 2-batch chunk (R12 proven) -----------
__global__ __launch_bounds__(512, 3) void blend_kernel(const float* __restrict__ masks,
                                                       float* __restrict__ out, int b0) {
    __shared__ float4 sA4[MM][2];
    __shared__ float  sred[4][256];
    int b   = b0 + (blockIdx.x >> 7);
    int loc = blockIdx.x & 127;
    int tid = threadIdx.x;
    int half = tid >> 8;              // 0: planes 0-15, 1: planes 16-31
    int pi   = tid & 255;

    if (tid < MM) {
        const float* Hp = g_Hm + (b*MM + tid)*6;
        sA4[tid][0] = make_float4(127.5f*Hp[0], 127.5f*Hp[1], 127.5f*(Hp[2]+1.f), 0.f);
        sA4[tid][1] = make_float4(63.5f*Hp[3],  63.5f*Hp[4],  63.5f*(Hp[5]+1.f),  0.f);
    }
    __syncthreads();

    int pix = loc*256 + pi;
    int y = pix >> 8, x = pix & (WW-1);
    float gxx = -1.f + 2.f*(float)x*(1.f/(float)(WW-1));
    float gyy = -1.f + 2.f*(float)y*(1.f/(float)(HH-1));

    const float* mbase = masks + (size_t)b*MM*HW + (size_t)half*16*HW + pix;
    const float4* ip = g_imgp + (size_t)b*PH*PW;
    float se = 0.f, o0 = 0.f, o1 = 0.f, o2 = 0.f;
#pragma unroll 8
    for (int mi = 0; mi < 16; mi++) {
        int m = half*16 + mi;
        float e = __expf(mbase[(size_t)mi*HW]);
        se += e;
        float4 cA = sA4[m][0];
        float4 cB = sA4[m][1];
        float ix = fmaf(cA.x, gxx, fmaf(cA.y, gyy, cA.z));
        float iy = fmaf(cB.x, gxx, fmaf(cB.y, gyy, cB.z));
        float x0f = floorf(ix), y0f = floorf(iy);
        float wx = ix - x0f, wy = iy - y0f;
        int xc = (int)fminf(fmaxf(x0f, -2.f), (float)WW);
        int yc = (int)fminf(fmaxf(y0f, -2.f), (float)HH);
        const float4* p00 = ip + (size_t)(yc+2)*PW + (xc+2);
        float4 c00 = p00[0];
        float4 c10 = p00[1];
        float4 c01 = p00[PW];
        float4 c11 = p00[PW+1];
        float w11 = wx*wy;
        float w10 = wx - w11;
        float w01 = wy - w11;
        float w00 = 1.f - wx - w01;
        o0 = fmaf(e, c00.x*w00 + c10.x*w10 + c01.x*w01 + c11.x*w11, o0);
        o1 = fmaf(e, c00.y*w00 + c10.y*w10 + c01.y*w01 + c11.y*w11, o1);
        o2 = fmaf(e, c00.z*w00 + c10.z*w10 + c01.z*w01 + c11.z*w11, o2);
    }

    if (half) { sred[0][pi]=se; sred[1][pi]=o0; sred[2][pi]=o1; sred[3][pi]=o2; }
    __syncthreads();
    if (!half) {
        se += sred[0][pi]; o0 += sred[1][pi]; o1 += sred[2][pi]; o2 += sred[3][pi];
        float inv = 1.f/se;
        out[((size_t)b*3 + 0)*HW + pix] = o0*inv;
        out[((size_t)b*3 + 1)*HW + pix] = o1*inv;
        out[((size_t)b*3 + 2)*HW + pix] = o2*inv;
    }
}

// ---------------- launch: chunked forked-stream pipeline (R12 structure) -----
extern "C" void kernel_launch(void* const* d_in, const int* in_sizes, int n_in,
                              void* d_out, int out_size) {
    const float* img      = (const float*)d_in[0];
    const float* masks    = (const float*)d_in[1];
    const float* disp     = (const float*)d_in[2];
    const float* intrs    = (const float*)d_in[3];
    const float* baseline = (const float*)d_in[4];
    float* out = (float*)d_out;

    // Fresh stream + events each call (capture-safe; intentionally not destroyed
    // so captured graph nodes stay valid; kernel_launch runs only a few times).
    cudaStream_t sB;
    cudaStreamCreateWithFlags(&sB, cudaStreamNonBlocking);
    cudaEvent_t eFork, ePool[NCHUNK];
    cudaEventCreateWithFlags(&eFork, cudaEventDisableTiming);
    for (int k = 0; k < NCHUNK; k++)
        cudaEventCreateWithFlags(&ePool[k], cudaEventDisableTiming);

    // fork: pool chunks on sB (residency-capped blocks -> true concurrency)
    cudaEventRecord(eFork, 0);
    cudaStreamWaitEvent(sB, eFork, 0);
    for (int k = 0; k < NCHUNK; k++) {
        pool_kernel<<<BCHUNK*POOL_PB/2, 512, 0, sB>>>(img, k*BCHUNK);
        cudaEventRecord(ePool[k], sB);
    }

    // stream 0: plane partials -> homographies (+ border zero)
    plane_kernel<<<PLANE_BLKS, 256>>>(masks, disp, intrs, baseline);
    finalize_kernel<<<BB*MM, 64>>>(intrs, baseline);

    // join: blend chunk k after pool chunk k (finalize ordered by stream 0)
    for (int k = 0; k < NCHUNK; k++) {
        cudaStreamWaitEvent(0, ePool[k], 0);
        blend_kernel<<<BCHUNK*128, 512>>>(masks, out, k*BCHUNK);
    }
}

// round 16
// speedup vs baseline: 1.6103x; 1.0517x over previous
#include <cuda_runtime.h>
#include <cuda_fp16.h>
#include <math.h>

// Fixed problem shapes
#define BB 8
#define CC 3
#define HF 1024
#define WF 2048
#define MM 32
#define HH 128
#define WW 256
#define HW (HH*WW)

// padded pooled image (2-px zero border each side), fp16 storage
#define PW (WW+4)
#define PH (HH+4)

#define NCH 64
#define CHSZ (HW/NCH)              // 512 samples per chunk
#define WIN  (3*CHSZ)              // 1536-wide contiguous j-window
#define HALO 257

#define BORDER_PER_B (4*PW + 4*HH)             // 1552
#define BORDER_ELEMS (BB*BORDER_PER_B)         // 12416

#define PLANE_BLKS (BB*NCH)                    // 512
#define POOL_PB    (CC*HH*WW/32)               // 3072 pool blocks per batch
#define BCHUNK     2                           // batches per pipeline chunk
#define NCHUNK     (BB/BCHUNK)                 // 4 chunks

// ---------------- scratch ----------------------------------------------------
__device__ uint2  g_imgp[BB*PH*PW];          // pooled image: {h(c0),h(c1)},{h(c2),pad}
__device__ float  g_Hm  [BB*MM*6];           // homography top-2 rows
__device__ float  g_part[BB*MM*5*NCH];       // partial sums [bm][5][NCH]

// ---------------- kernel 1: plane partials -----------------------------------
__global__ __launch_bounds__(256) void plane_kernel(const float* __restrict__ masks,
                                                    const float* __restrict__ disp,
                                                    const float* __restrict__ intrs,
                                                    const float* __restrict__ baseline) {
    __shared__ float  sdep[WIN + 2*HALO];
    __shared__ float4 sdn [CHSZ];
    int bid = blockIdx.x;
    int tid = threadIdx.x;

    int bb = bid / NCH, ch = bid % NCH;
    float f  = 0.5f*(intrs[bb*9 + 0] + intrs[bb*9 + 4]);
    float sc = baseline[bb] * f * (1.f/2048.f);
    const float* dsp = disp + (size_t)bb*HW;
    int S = ch*CHSZ;
    int jbase = 3*S;

    // phase 0: coalesced depth window
    for (int k = tid; k < WIN + 2*HALO; k += 256) {
        int jj = jbase + k - HALO;
        jj = min(max(jj, 0), 3*HW - 1);
        sdep[k] = __fdividef(sc, dsp[jj & (HW-1)]);
    }
    __syncthreads();

    // phase 1: normals from smem (faithful .view(B,h*w,3) reinterpret)
    for (int k = tid; k < CHSZ; k += 256) {
        int i = S + k;
        float4 v;
        v.x = __fdividef(sc, dsp[i]);
        int k3 = 3*k;
        float nv[3];
#pragma unroll
        for (int tc = 0; tc < 3; tc++) {
            int j  = jbase + k3 + tc;
            int c  = j >> 15;
            int p  = j & (HW-1);
            int px = p & (WW-1), py = p >> 8;
            int kk = HALO + k3 + tc;
            float dxp = (px < WW-1) ? sdep[kk+1]  : 0.f;
            float dxm = (px > 0)    ? sdep[kk-1]  : 0.f;
            float dyp = (py < HH-1) ? sdep[kk+WW] : 0.f;
            float dym = (py > 0)    ? sdep[kk-WW] : 0.f;
            float gx = 0.5f*(dxp - dxm);
            float gy = 0.5f*(dyp - dym);
            float inv = rsqrtf(gx*gx + gy*gy + 1.f);
            nv[tc] = (c == 0) ? -gx*inv : ((c == 1) ? -gy*inv : inv);
        }
        v.y = nv[0]; v.z = nv[1]; v.w = nv[2];
        sdn[k] = v;
    }
    __syncthreads();

    // phase 2: warp w handles planes w, w+8, w+16, w+24
    int wrp = tid >> 5, lane = tid & 31;
    const float* mb = masks + (size_t)bb*MM*HW + (size_t)S;
#pragma unroll
    for (int mi = 0; mi < 4; mi++) {
        int m = wrp + mi*8;
        const float* mp = mb + (size_t)m*HW;
        float se=0.f, sd=0.f, s0=0.f, s1=0.f, s2=0.f;
#pragma unroll
        for (int jj = 0; jj < 16; jj++) {
            int k = lane + jj*32;
            float e = __expf(mp[k]);     // no max-sub: ratio-invariant, safe range
            float4 v = sdn[k];
            se += e;
            sd = fmaf(e, v.x, sd);
            s0 = fmaf(e, v.y, s0);
            s1 = fmaf(e, v.z, s1);
            s2 = fmaf(e, v.w, s2);
        }
#pragma unroll
        for (int off = 16; off; off >>= 1) {
            se += __shfl_down_sync(0xffffffffu, se, off);
            sd += __shfl_down_sync(0xffffffffu, sd, off);
            s0 += __shfl_down_sync(0xffffffffu, s0, off);
            s1 += __shfl_down_sync(0xffffffffu, s1, off);
            s2 += __shfl_down_sync(0xffffffffu, s2, off);
        }
        if (lane == 0) {
            float* pp = g_part + ((size_t)(bb*MM + m)*5)*NCH + ch;
            pp[0*NCH]=se; pp[1*NCH]=sd; pp[2*NCH]=s0; pp[3*NCH]=s1; pp[4*NCH]=s2;
        }
    }
}

// ---------------- kernel 2: pool for a 2-batch chunk (fp16 output) -----------
__global__ __launch_bounds__(256) void pool_kernel(const float* __restrict__ img, int b0) {
    __shared__ float sm[256];
    int tid = threadIdx.x;
    int lane = tid & 31, r = tid >> 5;
    int b  = b0 + blockIdx.x / POOL_PB;
    int q  = blockIdx.x % POOL_PB;
    int l  = q * 32;
    int x0 = l & (WW-1);
    int t  = l >> 8;
    int y  = t & (HH-1);
    int c  = t >> 7;

    const float4* p = (const float4*)(img +
        (((size_t)(b*CC + c)*HF + (size_t)y*8 + r)*WF) + (size_t)(x0 + lane)*8);
    float4 a = __ldcs(p), q4 = __ldcs(p + 1);   // streaming: don't pollute L1
    sm[r*32 + lane] = a.x+a.y+a.z+a.w + q4.x+q4.y+q4.z+q4.w;
    __syncthreads();
    if (tid < 32) {
        float acc = 0.f;
#pragma unroll
        for (int rr = 0; rr < 8; rr++) acc += sm[rr*32 + tid];
        __half* px = (__half*)&g_imgp[(size_t)b*PH*PW + (size_t)(y+2)*PW + (x0 + tid + 2)];
        px[c] = __float2half_rn(acc * (1.f/64.f));
    }
}

// ---------------- kernel 3: finalize homographies + border zero --------------
__global__ void finalize_kernel(const float* __restrict__ intrs,
                                const float* __restrict__ baseline) {
    int bm = blockIdx.x;              // 256 blocks = (b,m)
    int c  = threadIdx.x;             // 64 threads
    int lane = c & 31, w = c >> 5;

    int gt = bm*64 + c;
    if (gt < BORDER_ELEMS) {
        int b = gt / BORDER_PER_B;
        int r = gt % BORDER_PER_B;
        int cell;
        if (r < 2*PW)       cell = r;
        else if (r < 4*PW)  cell = (PH-2)*PW + (r - 2*PW);
        else {
            int rr = r - 4*PW;
            int row = rr >> 2, col = rr & 3;
            int cc = (col < 2) ? col : (PW-4 + col);
            cell = (2+row)*PW + cc;
        }
        g_imgp[(size_t)b*PH*PW + cell] = make_uint2(0u, 0u);
    }

    const float* pp = g_part + (size_t)bm*5*NCH;
    float v[5];
#pragma unroll
    for (int s = 0; s < 5; s++) v[s] = pp[s*NCH + c];
#pragma unroll
    for (int off = 16; off; off >>= 1)
#pragma unroll
        for (int s = 0; s < 5; s++) v[s] += __shfl_down_sync(0xffffffffu, v[s], off);
    __shared__ float sw[2][5];
    if (lane == 0)
#pragma unroll
        for (int s = 0; s < 5; s++) sw[w][s] = v[s];
    __syncthreads();
    if (c == 0) {
        float se = sw[0][0]+sw[1][0];
        float sd = sw[0][1]+sw[1][1];
        float s0 = sw[0][2]+sw[1][2];
        float s1 = sw[0][3]+sw[1][3];
        float s2 = sw[0][4]+sw[1][4];
        int b = bm / MM;
        float inv = 1.f/se;
        float d  = sd*inv;
        float n0 = s0*inv, n1 = s1*inv, n2 = s2*inv;
        float f  = intrs[b*9+0], g = intrs[b*9+4];
        float cx = intrs[b*9+2], cy = intrs[b*9+5];
        float bl = baseline[b];
        float t0 = bl*n0/d, t1 = bl*n1/d, t2 = bl*n2/d;
        float* o = g_Hm + bm*6;
        o[0] = 1.f + cx*t0/f;
        o[1] = cx*t1/g;
        o[2] = cx*t2 - cx*cx*t0/f - cx*cy*t1/g;
        o[3] = cy*t0/f;
        o[4] = 1.f + cy*t1/g;
        o[5] = cy*t2 - cx*cy*t0/f - cy*cy*t1/g;
    }
}

// ---------------- fp16 corner fetch ------------------------------------------
__device__ __forceinline__ float3 ldc3(const uint2* p) {
    uint2 v = *p;
    __half2 h01 = *reinterpret_cast<__half2*>(&v.x);
    float2  f01 = __half22float2(h01);
    float   f2  = __half2float(*reinterpret_cast<__half*>(&v.y));
    return make_float3(f01.x, f01.y, f2);
}

// ---------------- kernel 4: blend for a 2-batch chunk (fp16 corners) ---------
__global__ __launch_bounds__(512, 3) void blend_kernel(const float* __restrict__ masks,
                                                       float* __restrict__ out, int b0) {
    __shared__ float4 sA4[MM][2];
    __shared__ float  sred[4][256];
    int b   = b0 + (blockIdx.x >> 7);
    int loc = blockIdx.x & 127;
    int tid = threadIdx.x;
    int half_ = tid >> 8;             // 0: planes 0-15, 1: planes 16-31
    int pi   = tid & 255;

    if (tid < MM) {
        const float* Hp = g_Hm + (b*MM + tid)*6;
        sA4[tid][0] = make_float4(127.5f*Hp[0], 127.5f*Hp[1], 127.5f*(Hp[2]+1.f), 0.f);
        sA4[tid][1] = make_float4(63.5f*Hp[3],  63.5f*Hp[4],  63.5f*(Hp[5]+1.f),  0.f);
    }
    __syncthreads();

    int pix = loc*256 + pi;
    int y = pix >> 8, x = pix & (WW-1);
    float gxx = -1.f + 2.f*(float)x*(1.f/(float)(WW-1));
    float gyy = -1.f + 2.f*(float)y*(1.f/(float)(HH-1));

    const float* mbase = masks + (size_t)b*MM*HW + (size_t)half_*16*HW + pix;
    const uint2* ip = g_imgp + (size_t)b*PH*PW;
    float se = 0.f, o0 = 0.f, o1 = 0.f, o2 = 0.f;
#pragma unroll 8
    for (int mi = 0; mi < 16; mi++) {
        int m = half_*16 + mi;
        float e = __expf(mbase[(size_t)mi*HW]);
        se += e;
        float4 cA = sA4[m][0];
        float4 cB = sA4[m][1];
        float ix = fmaf(cA.x, gxx, fmaf(cA.y, gyy, cA.z));
        float iy = fmaf(cB.x, gxx, fmaf(cB.y, gyy, cB.z));
        float x0f = floorf(ix), y0f = floorf(iy);
        float wx = ix - x0f, wy = iy - y0f;
        int xc = (int)fminf(fmaxf(x0f, -2.f), (float)WW);
        int yc = (int)fminf(fmaxf(y0f, -2.f), (float)HH);
        const uint2* p00 = ip + (size_t)(yc+2)*PW + (xc+2);
        float3 c00 = ldc3(p00);
        float3 c10 = ldc3(p00 + 1);
        float3 c01 = ldc3(p00 + PW);
        float3 c11 = ldc3(p00 + PW + 1);
        float w11 = wx*wy;
        float w10 = wx - w11;
        float w01 = wy - w11;
        float w00 = 1.f - wx - w01;
        o0 = fmaf(e, c00.x*w00 + c10.x*w10 + c01.x*w01 + c11.x*w11, o0);
        o1 = fmaf(e, c00.y*w00 + c10.y*w10 + c01.y*w01 + c11.y*w11, o1);
        o2 = fmaf(e, c00.z*w00 + c10.z*w10 + c01.z*w01 + c11.z*w11, o2);
    }

    if (half_) { sred[0][pi]=se; sred[1][pi]=o0; sred[2][pi]=o1; sred[3][pi]=o2; }
    __syncthreads();
    if (!half_) {
        se += sred[0][pi]; o0 += sred[1][pi]; o1 += sred[2][pi]; o2 += sred[3][pi];
        float inv = 1.f/se;
        out[((size_t)b*3 + 0)*HW + pix] = o0*inv;
        out[((size_t)b*3 + 1)*HW + pix] = o1*inv;
        out[((size_t)b*3 + 2)*HW + pix] = o2*inv;
    }
}

// ---------------- launch: chunked forked-stream pipeline (R12 structure) -----
extern "C" void kernel_launch(void* const* d_in, const int* in_sizes, int n_in,
                              void* d_out, int out_size) {
    const float* img      = (const float*)d_in[0];
    const float* masks    = (const float*)d_in[1];
    const float* disp     = (const float*)d_in[2];
    const float* intrs    = (const float*)d_in[3];
    const float* baseline = (const float*)d_in[4];
    float* out = (float*)d_out;

    // Fresh stream + events each call (capture-safe; intentionally not destroyed
    // so captured graph nodes stay valid; kernel_launch runs only a few times).
    cudaStream_t sB;
    cudaStreamCreateWithFlags(&sB, cudaStreamNonBlocking);
    cudaEvent_t eFork, ePool[NCHUNK];
    cudaEventCreateWithFlags(&eFork, cudaEventDisableTiming);
    for (int k = 0; k < NCHUNK; k++)
        cudaEventCreateWithFlags(&ePool[k], cudaEventDisableTiming);

    // fork: pool chunks on sB
    cudaEventRecord(eFork, 0);
    cudaStreamWaitEvent(sB, eFork, 0);
    for (int k = 0; k < NCHUNK; k++) {
        pool_kernel<<<BCHUNK*POOL_PB, 256, 0, sB>>>(img, k*BCHUNK);
        cudaEventRecord(ePool[k], sB);
    }

    // stream 0: plane partials -> homographies (+ border zero)
    plane_kernel<<<PLANE_BLKS, 256>>>(masks, disp, intrs, baseline);
    finalize_kernel<<<BB*MM, 64>>>(intrs, baseline);

    // join: blend chunk k after pool chunk k (finalize ordered by stream 0)
    for (int k = 0; k < NCHUNK; k++) {
        cudaStreamWaitEvent(0, ePool[k], 0);
        blend_kernel<<<BCHUNK*128, 512>>>(masks, out, k*BCHUNK);
    }
}